// round 1
// baseline (speedup 1.0000x reference)
#include <cuda_runtime.h>

// NbitTreeDecoder: complete 4-ary tree (every flag has exactly 4 of 8 bits set).
// Leaf i in [0, 4^10): ancestor node index at level t is i >> (2*(10-t)),
// branch digit d_t = (i >> (2*(9-t))) & 3, nibble j_t = position of d_t-th
// set bit of that node's flag. Code X = j_0..j_9 (3 bits each, j_0 MSB).
// Then 30-bit bit-reversal (= __brev(X) >> 2), split into 3x10-bit fields,
// float scale+offset.

static __device__ __forceinline__ unsigned nth_set_bit(unsigned f, unsigned d) {
    // position of d-th (0-based) set bit; f guaranteed to have >= d+1 bits set
    unsigned g = f;
    g = (d > 0u) ? (g & (g - 1u)) : g;
    g = (d > 1u) ? (g & (g - 1u)) : g;
    g = (d > 2u) ? (g & (g - 1u)) : g;
    return (unsigned)__ffs(g) - 1u;
}

__global__ void __launch_bounds__(256)
nbit_tree_decode_kernel(const int* __restrict__ flags,
                        const float* __restrict__ offset,
                        const float* __restrict__ scale,
                        float* __restrict__ out) {
    const unsigned n9 = blockIdx.x * blockDim.x + threadIdx.x;  // level-9 node, [0, 4^9)

    // (4^t - 1)/3 prefix offsets into flags for levels 0..9
    const unsigned OFF0 = 0u,     OFF1 = 1u,     OFF2 = 5u,    OFF3 = 21u,
                   OFF4 = 85u,    OFF5 = 341u,   OFF6 = 1365u, OFF7 = 5461u,
                   OFF8 = 21845u, OFF9 = 87381u;
    const unsigned OFF[9] = {OFF0, OFF1, OFF2, OFF3, OFF4, OFF5, OFF6, OFF7, OFF8};

    const float s0 = scale[0],  s1 = scale[1],  s2 = scale[2];
    const float o0 = offset[0], o1 = offset[1], o2 = offset[2];

    // Walk levels 0..8 once per thread (shared prefix for 4 leaves)
    unsigned prefix = 0u;
#pragma unroll
    for (int t = 0; t < 9; t++) {
        const unsigned nt   = n9 >> (18 - 2 * t);          // ancestor node at level t
        const unsigned flag = (unsigned)__ldg(flags + OFF[t] + nt);
        const unsigned d    = (n9 >> (16 - 2 * t)) & 3u;   // branch digit at level t
        prefix = (prefix << 3) | nth_set_bit(flag, d);
    }

    const unsigned flag9 = (unsigned)__ldg(flags + OFF9 + n9);

    float vals[12];
    unsigned f = flag9;
#pragma unroll
    for (int r = 0; r < 4; r++) {
        const unsigned j  = (unsigned)__ffs(f) - 1u;  // r-th set bit (ascending)
        f &= f - 1u;
        const unsigned X  = (prefix << 3) | j;        // 30-bit code
        const unsigned Xr = __brev(X) >> 2;           // 30-bit reversal
        vals[3 * r + 0] = fmaf((float)(Xr & 1023u),         s0, o0);
        vals[3 * r + 1] = fmaf((float)((Xr >> 10) & 1023u), s1, o1);
        vals[3 * r + 2] = fmaf((float)(Xr >> 20),           s2, o2);
    }

    // 4 leaves * 3 floats = 48 contiguous bytes, 16B-aligned -> 3x float4
    float4* outv = reinterpret_cast<float4*>(out + (size_t)n9 * 12u);
    outv[0] = make_float4(vals[0], vals[1],  vals[2],  vals[3]);
    outv[1] = make_float4(vals[4], vals[5],  vals[6],  vals[7]);
    outv[2] = make_float4(vals[8], vals[9],  vals[10], vals[11]);
}

extern "C" void kernel_launch(void* const* d_in, const int* in_sizes, int n_in,
                              void* d_out, int out_size) {
    const int*   flags  = (const int*)d_in[0];
    const float* offset = (const float*)d_in[1];
    const float* scale  = (const float*)d_in[2];
    float*       out    = (float*)d_out;

    const int n9 = 262144;  // 4^9 level-9 nodes; each thread emits 4 leaves
    nbit_tree_decode_kernel<<<n9 / 256, 256>>>(flags, offset, scale, out);
}